// round 10
// baseline (speedup 1.0000x reference)
#include <cuda_runtime.h>
#include <cuda_fp16.h>
#include <cstdint>

// ---------------------------------------------------------------------------
// Problem constants (B=8192, N_IN=1024, N=2048)
// ---------------------------------------------------------------------------
#define FN   2048
#define FT   256
#define GM   8192
#define GN   4096
#define GK   1024

// Bank-conflict-free smem swizzle (bijection; XOR bits[4:6) into [0:4))
#define SW(i) ((i) ^ ((((i) >> 4) & 3) * 5))

// Static scratch (no allocs allowed)
__device__ float  g_mul[8192ULL * 4096ULL];   // GEMM output (B, 2N)
__device__ __half g_Af[8192ULL * 1024ULL];
__device__ __half g_Bf[4096ULL * 1024ULL];

// ---------------------------------------------------------------------------
// fp32 -> fp16 convert (vectorized)
// ---------------------------------------------------------------------------
__global__ void cvt_kernel(const float4* __restrict__ src,
                           __half* __restrict__ dst, int n4)
{
    int i = blockIdx.x * blockDim.x + threadIdx.x;
    if (i < n4) {
        float4 v = src[i];
        __half2* d = (__half2*)(dst + 4 * (size_t)i);
        d[0] = __floats2half2_rn(v.x, v.y);
        d[1] = __floats2half2_rn(v.z, v.w);
    }
}

// ---------------------------------------------------------------------------
// fp16 GEMM (unchanged from R9): 128x256x32, cp.async double-buffer
// ---------------------------------------------------------------------------
__device__ __forceinline__ void cp_async16(void* smem, const void* gmem)
{
    uint32_t s = (uint32_t)__cvta_generic_to_shared(smem);
    asm volatile("cp.async.cg.shared.global [%0], [%1], 16;\n" :: "r"(s), "l"(gmem));
}

__device__ __forceinline__ void ldsm_x4(uint32_t* r, const void* p)
{
    uint32_t s = (uint32_t)__cvta_generic_to_shared(p);
    asm volatile("ldmatrix.sync.aligned.m8n8.x4.shared.b16 {%0,%1,%2,%3}, [%4];\n"
                 : "=r"(r[0]), "=r"(r[1]), "=r"(r[2]), "=r"(r[3]) : "r"(s));
}

__device__ __forceinline__ void mma16816(float* c, const uint32_t* a, const uint32_t* b)
{
    asm volatile(
        "mma.sync.aligned.m16n8k16.row.col.f32.f16.f16.f32 "
        "{%0,%1,%2,%3}, {%4,%5,%6,%7}, {%8,%9}, {%0,%1,%2,%3};\n"
        : "+f"(c[0]), "+f"(c[1]), "+f"(c[2]), "+f"(c[3])
        : "r"(a[0]), "r"(a[1]), "r"(a[2]), "r"(a[3]), "r"(b[0]), "r"(b[1]));
}

#define SROW 40
#define GA_H (128 * SROW)
#define GB_H (256 * SROW)
#define GEMM_SMEM ((2 * GA_H + 2 * GB_H) * 2)

extern __shared__ char dynsm[];

__global__ __launch_bounds__(256, 1) void gemm_fp16(
    const __half* __restrict__ Af, const __half* __restrict__ Bf,
    float* __restrict__ C)
{
    __half* As = (__half*)dynsm;
    __half* Bs = (__half*)dynsm + 2 * GA_H;

    const int tid  = threadIdx.x;
    const int wid  = tid >> 5, lane = tid & 31;
    const int wm   = wid >> 2, wn = wid & 3;
    const int bm   = blockIdx.y * 128, bn = blockIdx.x * 256;

    const int NIT = GK / 32;

    float acc[4][8][4];
    #pragma unroll
    for (int mi = 0; mi < 4; ++mi)
        #pragma unroll
        for (int ni = 0; ni < 8; ++ni)
            #pragma unroll
            for (int j = 0; j < 4; ++j) acc[mi][ni][j] = 0.0f;

    auto load_tiles = [&](int st, int it) {
        int kk = it * 32;
        #pragma unroll
        for (int j = 0; j < 2; ++j) {
            int c   = tid + j * 256;
            int row = c >> 2;
            int off = (c & 3) * 8;
            cp_async16(&As[st * GA_H + row * SROW + off],
                       Af + (size_t)(bm + row) * GK + kk + off);
        }
        #pragma unroll
        for (int j = 0; j < 4; ++j) {
            int c   = tid + j * 256;
            int row = c >> 2;
            int off = (c & 3) * 8;
            cp_async16(&Bs[st * GB_H + row * SROW + off],
                       Bf + (size_t)(bn + row) * GK + kk + off);
        }
        asm volatile("cp.async.commit_group;\n");
    };

    load_tiles(0, 0);

    for (int it = 0; it < NIT; ++it) {
        int st = it & 1;
        if (it + 1 < NIT) {
            load_tiles(st ^ 1, it + 1);
            asm volatile("cp.async.wait_group 1;\n");
        } else {
            asm volatile("cp.async.wait_group 0;\n");
        }
        __syncthreads();

        #pragma unroll
        for (int ks = 0; ks < 2; ++ks) {
            uint32_t a[4][4], b[8][2];
            int ra = wm * 64 + (lane & 7) + ((lane & 8) ? 8 : 0);
            int ca = ks * 16 + ((lane & 16) ? 8 : 0);
            #pragma unroll
            for (int mi = 0; mi < 4; ++mi)
                ldsm_x4(a[mi], &As[st * GA_H + (ra + mi * 16) * SROW + ca]);
            int rb = wn * 64 + (lane & 7) + ((lane & 16) ? 8 : 0);
            int cb = ks * 16 + ((lane & 8) ? 8 : 0);
            #pragma unroll
            for (int g = 0; g < 4; ++g) {
                uint32_t r[4];
                ldsm_x4(r, &Bs[st * GB_H + (rb + g * 16) * SROW + cb]);
                b[2 * g][0] = r[0]; b[2 * g][1] = r[1];
                b[2 * g + 1][0] = r[2]; b[2 * g + 1][1] = r[3];
            }
            #pragma unroll
            for (int mi = 0; mi < 4; ++mi)
                #pragma unroll
                for (int ni = 0; ni < 8; ++ni)
                    mma16816(acc[mi][ni], a[mi], b[ni]);
        }
        __syncthreads();
    }

    #pragma unroll
    for (int mi = 0; mi < 4; ++mi) {
        #pragma unroll
        for (int ni = 0; ni < 8; ++ni) {
            int row = bm + wm * 64 + mi * 16 + (lane >> 2);
            int col = bn + wn * 64 + ni * 8 + (lane & 3) * 2;
            float2* p0 = (float2*)(C + (size_t)row * GN + col);
            float2* p1 = (float2*)(C + (size_t)(row + 8) * GN + col);
            *p0 = make_float2(acc[mi][ni][0], acc[mi][ni][1]);
            *p1 = make_float2(acc[mi][ni][2], acc[mi][ni][3]);
        }
    }
}

// ---------------------------------------------------------------------------
// complex helpers
// ---------------------------------------------------------------------------
__device__ __forceinline__ float2 cadd(float2 a, float2 b)
{ return make_float2(a.x + b.x, a.y + b.y); }
__device__ __forceinline__ float2 csub(float2 a, float2 b)
{ return make_float2(a.x - b.x, a.y - b.y); }
__device__ __forceinline__ float2 cmul(float2 a, float2 b)
{ return make_float2(a.x * b.x - a.y * b.y, a.x * b.y + a.y * b.x); }
__device__ __forceinline__ float2 cmulc(float2 a, float2 b)   // a * conj(b)
{ return make_float2(a.x * b.x + a.y * b.y, a.y * b.x - a.x * b.y); }

// twiddle fetch with sign fold: table holds tw[k]=exp(-2pi i k/2048), k<1024
__device__ __forceinline__ float2 twget(const float2* tw, int e)
{
    float2 w = tw[e & 1023];
    if (e & 1024) { w.x = -w.x; w.y = -w.y; }
    return w;
}

// ---------------------------------------------------------------------------
// DFT-8 in registers (even/odd DFT-4 + W8 combine). INV = conjugated.
// ---------------------------------------------------------------------------
template<bool INV>
__device__ __forceinline__ void dft8(float2* a)
{
    const float C = 0.70710678118654752f;
    float2 t0 = cadd(a[0], a[4]), t1 = csub(a[0], a[4]);
    float2 t2 = cadd(a[2], a[6]), t3 = csub(a[2], a[6]);
    float2 u0 = cadd(a[1], a[5]), u1 = csub(a[1], a[5]);
    float2 u2 = cadd(a[3], a[7]), u3 = csub(a[3], a[7]);
    float2 E0 = cadd(t0, t2), E2 = csub(t0, t2);
    float2 O0 = cadd(u0, u2), O2 = csub(u0, u2);
    float2 E1, E3, O1, O3, w1o, w2o, w3o;
    if (!INV) {
        E1 = make_float2(t1.x + t3.y, t1.y - t3.x);   // t1 - i t3
        E3 = make_float2(t1.x - t3.y, t1.y + t3.x);
        O1 = make_float2(u1.x + u3.y, u1.y - u3.x);
        O3 = make_float2(u1.x - u3.y, u1.y + u3.x);
        w1o = make_float2(C * (O1.x + O1.y), C * (O1.y - O1.x));   // c(1-i)
        w2o = make_float2(O2.y, -O2.x);                            // -i
        w3o = make_float2(C * (O3.y - O3.x), -C * (O3.x + O3.y));  // -c(1+i)
    } else {
        E1 = make_float2(t1.x - t3.y, t1.y + t3.x);   // t1 + i t3
        E3 = make_float2(t1.x + t3.y, t1.y - t3.x);
        O1 = make_float2(u1.x - u3.y, u1.y + u3.x);
        O3 = make_float2(u1.x + u3.y, u1.y - u3.x);
        w1o = make_float2(C * (O1.x - O1.y), C * (O1.y + O1.x));   // c(1+i)
        w2o = make_float2(-O2.y, O2.x);                            // i
        w3o = make_float2(-C * (O3.x + O3.y), C * (O3.x - O3.y));  // -c(1-i)
    }
    a[0] = cadd(E0, O0); a[4] = csub(E0, O0);
    a[1] = cadd(E1, w1o); a[5] = csub(E1, w1o);
    a[2] = cadd(E2, w2o); a[6] = csub(E2, w2o);
    a[3] = cadd(E3, w3o); a[7] = csub(E3, w3o);
}

// One radix-8 Stockham stage (smem -> smem), m in {8, 64}
template<bool INV>
__device__ __forceinline__ void r8_stage(const float2* x, float2* y,
                                         const float2* tw, int tid, int m)
{
    int t = tid;
    int pm = t & ~(m - 1);
    float2 a[8];
    #pragma unroll
    for (int q = 0; q < 8; ++q) a[q] = x[SW(t + (q << 8))];
    dft8<INV>(a);
    int base = t + 7 * pm;
    y[SW(base)] = a[0];
    #pragma unroll
    for (int q = 1; q < 8; ++q) {
        float2 w = twget(tw, q * pm);
        y[SW(base + q * m)] = INV ? cmulc(a[q], w) : cmul(w, a[q]);
    }
}

// ---------------------------------------------------------------------------
// Block reduction of (sr, si, sq) -> f = 2/sq * (sr, si)   (8 warps)
// ---------------------------------------------------------------------------
__device__ __forceinline__ float2 block_reduce_f(
    float sr, float si, float sq, float (*red)[8], int tid)
{
    #pragma unroll
    for (int o = 16; o; o >>= 1) {
        sr += __shfl_xor_sync(0xffffffffu, sr, o);
        si += __shfl_xor_sync(0xffffffffu, si, o);
        sq += __shfl_xor_sync(0xffffffffu, sq, o);
    }
    int w = tid >> 5;
    if ((tid & 31) == 0) { red[0][w] = sr; red[1][w] = si; red[2][w] = sq; }
    __syncthreads();
    sr = si = sq = 0.f;
    #pragma unroll
    for (int i = 0; i < 8; ++i) { sr += red[0][i]; si += red[1][i]; sq += red[2][i]; }
    __syncthreads();
    float f = 2.0f / sq;
    return make_float2(f * sr, f * si);
}

// ---------------------------------------------------------------------------
// Fused URNN pipeline. 1 CTA = 1 row. Radix-8 Stockham (8,8,8,4).
// ---------------------------------------------------------------------------
__global__ __launch_bounds__(FT, 5) void urnn_fused_kernel(
    const float* __restrict__ state, const float* __restrict__ gin,
    const float* __restrict__ b_h,
    const float* __restrict__ d1w, const float* __restrict__ r1re, const float* __restrict__ r1im,
    const float* __restrict__ d2w, const float* __restrict__ r2re, const float* __restrict__ r2im,
    const float* __restrict__ d3w, const int* __restrict__ perm,
    float* __restrict__ out)
{
    __shared__ float2 bA[FN];
    __shared__ float2 bB[FN];
    __shared__ float2 tws[1024];
    __shared__ float  red[3][8];

    const int tid = threadIdx.x;
    const size_t b = blockIdx.x;
    const float* srow = state + b * (2 * FN);
    const float* grow = gin   + b * (2 * FN);
    float*       orow = out   + b * (2 * FN);

    for (int i = tid; i < 1024; i += FT) {
        float s, c;
        __sincosf(-6.283185307179586f * (float)i / (float)FN, &s, &c);
        tws[i] = make_float2(c, s);
    }
    __syncthreads();

    float2 *x = bA, *y = bB;

    // ---- FWD stage 0 (m=1, radix-8) fused with global load + diag1 ----
    {
        int t = tid;
        float2 a[8];
        #pragma unroll
        for (int q = 0; q < 8; ++q) {
            int i = t + (q << 8);
            float re = srow[i], im = srow[FN + i];
            float s, c; __sincosf(d1w[i], &s, &c);
            a[q] = make_float2(c * re - s * im, s * re + c * im);
        }
        dft8<false>(a);
        int base = 8 * t;
        y[SW(base)] = a[0];
        #pragma unroll
        for (int q = 1; q < 8; ++q)
            y[SW(base + q)] = cmul(twget(tws, q * t), a[q]);
    }
    __syncthreads();
    { float2* tmp = x; x = y; y = tmp; }

    // ---- FWD stages m=8, m=64 ----
    r8_stage<false>(x, y, tws, tid, 8);
    __syncthreads();
    { float2* tmp = x; x = y; y = tmp; }
    r8_stage<false>(x, y, tws, tid, 64);
    __syncthreads();
    { float2* tmp = x; x = y; y = tmp; }

    // ---- FWD radix-4 tail (m=512, no twiddles) fused with reflect-1 dots ----
    float sr1 = 0.f, si1 = 0.f, sq1 = 0.f;
    #pragma unroll
    for (int k = 0; k < 2; ++k) {
        int t = tid + k * 256;
        float2 a0 = x[SW(t)], a1 = x[SW(t + 512)],
               a2 = x[SW(t + 1024)], a3 = x[SW(t + 1536)];
        float2 t0 = cadd(a0, a2), t1 = csub(a0, a2);
        float2 t2 = cadd(a1, a3), t3 = csub(a1, a3);
        float2 b0 = cadd(t0, t2);
        float2 b2 = csub(t0, t2);
        float2 b1 = make_float2(t1.x + t3.y, t1.y - t3.x);
        float2 b3 = make_float2(t1.x - t3.y, t1.y + t3.x);
        y[SW(t)]        = b0;
        y[SW(t + 512)]  = b1;
        y[SW(t + 1024)] = b2;
        y[SW(t + 1536)] = b3;
        float2 bb[4] = {b0, b1, b2, b3};
        #pragma unroll
        for (int q = 0; q < 4; ++q) {
            int i = t + q * 512;
            float vr = r1re[i], vi = r1im[i];
            sr1 += bb[q].x * vr + bb[q].y * vi;
            si1 += bb[q].y * vr - bb[q].x * vi;
            sq1 += vr * vr + vi * vi;
        }
    }
    __syncthreads();
    { float2* tmp = x; x = y; y = tmp; }

    float2 f1 = block_reduce_f(sr1, si1, sq1, red, tid);

    // ---- IFFT stage 0 (m=1) fused with reflect1-update + perm + diag2 ----
    {
        int t = tid;
        float2 a[8];
        #pragma unroll
        for (int q = 0; q < 8; ++q) {
            int i = t + (q << 8);
            int p = perm[i];
            float2 zp = x[SW(p)];
            float vr = r1re[p], vi = r1im[p];
            zp.x -= f1.x * vr - f1.y * vi;
            zp.y -= f1.x * vi + f1.y * vr;
            float s, c; __sincosf(d2w[i], &s, &c);
            a[q] = make_float2(c * zp.x - s * zp.y, s * zp.x + c * zp.y);
        }
        dft8<true>(a);
        int base = 8 * t;
        y[SW(base)] = a[0];
        #pragma unroll
        for (int q = 1; q < 8; ++q)
            y[SW(base + q)] = cmulc(a[q], twget(tws, q * t));
    }
    __syncthreads();
    { float2* tmp = x; x = y; y = tmp; }

    // ---- IFFT stages m=8, m=64 ----
    r8_stage<true>(x, y, tws, tid, 8);
    __syncthreads();
    { float2* tmp = x; x = y; y = tmp; }
    r8_stage<true>(x, y, tws, tid, 64);
    __syncthreads();
    { float2* tmp = x; x = y; y = tmp; }

    // ---- IFFT radix-4 tail fused with reflect-2 dots ----
    float sr2 = 0.f, si2 = 0.f, sq2 = 0.f;
    #pragma unroll
    for (int k = 0; k < 2; ++k) {
        int t = tid + k * 256;
        float2 a0 = x[SW(t)], a1 = x[SW(t + 512)],
               a2 = x[SW(t + 1024)], a3 = x[SW(t + 1536)];
        float2 t0 = cadd(a0, a2), t1 = csub(a0, a2);
        float2 t2 = cadd(a1, a3), t3 = csub(a1, a3);
        float2 b0 = cadd(t0, t2);
        float2 b2 = csub(t0, t2);
        float2 b1 = make_float2(t1.x - t3.y, t1.y + t3.x);   // inverse: t1 + i t3
        float2 b3 = make_float2(t1.x + t3.y, t1.y - t3.x);
        y[SW(t)]        = b0;
        y[SW(t + 512)]  = b1;
        y[SW(t + 1024)] = b2;
        y[SW(t + 1536)] = b3;
        float2 bb[4] = {b0, b1, b2, b3};
        #pragma unroll
        for (int q = 0; q < 4; ++q) {
            int i = t + q * 512;
            float vr = r2re[i], vi = r2im[i];
            sr2 += bb[q].x * vr + bb[q].y * vi;
            si2 += bb[q].y * vr - bb[q].x * vi;
            sq2 += vr * vr + vi * vi;
        }
    }
    __syncthreads();
    { float2* tmp = x; x = y; y = tmp; }

    float2 f2 = block_reduce_f(sr2, si2, sq2, red, tid);

    // ---- final: reflect2-update + diag3*(1/N) + add inputs + modReLU ----
    const float invN = 1.0f / (float)FN;
    for (int i = tid; i < FN; i += FT) {
        float2 zc = x[SW(i)];
        float vr = r2re[i], vi = r2im[i];
        zc.x -= f2.x * vr - f2.y * vi;
        zc.y -= f2.x * vi + f2.y * vr;
        float s, c; __sincosf(d3w[i], &s, &c);
        float zr = (c * zc.x - s * zc.y) * invN;
        float zi = (s * zc.x + c * zc.y) * invN;
        float pr = grow[i]      + zr;
        float pi = grow[FN + i] + zi;
        float norm = sqrtf(pr * pr + pi * pi);
        float sc = fmaxf(norm + b_h[i], 0.0f) / (norm + 1e-6f);
        orow[i]      = pr * sc;
        orow[FN + i] = pi * sc;
    }
}

// ---------------------------------------------------------------------------
// Launch
// ---------------------------------------------------------------------------
extern "C" void kernel_launch(void* const* d_in, const int* in_sizes, int n_in,
                              void* d_out, int out_size)
{
    const float* inputs = (const float*)d_in[0];
    const float* state  = (const float*)d_in[1];
    const float* w_ih   = (const float*)d_in[2];
    const float* b_h    = (const float*)d_in[3];
    const float* d1w    = (const float*)d_in[4];
    const float* r1re   = (const float*)d_in[5];
    const float* r1im   = (const float*)d_in[6];
    const float* d2w    = (const float*)d_in[7];
    const float* r2re   = (const float*)d_in[8];
    const float* r2im   = (const float*)d_in[9];
    const float* d3w    = (const float*)d_in[10];
    const int*   perm   = (const int*)d_in[11];
    float* out = (float*)d_out;

    float *gmul; __half *Af, *Bf;
    cudaGetSymbolAddress((void**)&gmul, g_mul);
    cudaGetSymbolAddress((void**)&Af, g_Af);
    cudaGetSymbolAddress((void**)&Bf, g_Bf);

    cvt_kernel<<<(GM * GK / 4) / 256, 256>>>((const float4*)inputs, Af, GM * GK / 4);
    cvt_kernel<<<(GN * GK / 4) / 256, 256>>>((const float4*)w_ih,   Bf, GN * GK / 4);

    static bool attr_set = false;
    if (!attr_set) {
        cudaFuncSetAttribute(gemm_fp16, cudaFuncAttributeMaxDynamicSharedMemorySize,
                             GEMM_SMEM);
        attr_set = true;
    }
    dim3 ggrid(GN / 256, GM / 128);
    gemm_fp16<<<ggrid, 256, GEMM_SMEM>>>(Af, Bf, gmul);

    urnn_fused_kernel<<<GM, FT>>>(state, gmul, b_h,
                                  d1w, r1re, r1im,
                                  d2w, r2re, r2im,
                                  d3w, perm, out);
}

// round 11
// speedup vs baseline: 1.5441x; 1.5441x over previous
#include <cuda_runtime.h>
#include <cuda_fp16.h>
#include <cstdint>

// ---------------------------------------------------------------------------
// Problem constants (B=8192, N_IN=1024, N=2048)
// ---------------------------------------------------------------------------
#define FN   2048
#define FT   256
#define GM   8192
#define GN   4096
#define GK   1024

// Bank-conflict-free smem swizzle for radix-8 pattern set:
// fold bits[4:7) into [0:3) and bit6 into bit3. Pure XOR of high bits into
// low 4 => bijective. Conflict-free for: stride-1 16-aligned blocks,
// stage-0 writes (8t+q), m=8 writes (64j+8q+r), m=64 writes.
#define SW(i) ((i) ^ (((i) >> 4) & 7) ^ ((((i) >> 6) & 1) << 3))

// Static scratch (no allocs allowed)
__device__ float  g_mul[8192ULL * 4096ULL];   // GEMM output (B, 2N)
__device__ __half g_Af[8192ULL * 1024ULL];
__device__ __half g_Bf[4096ULL * 1024ULL];

// ---------------------------------------------------------------------------
// fp32 -> fp16 convert (vectorized)
// ---------------------------------------------------------------------------
__global__ void cvt_kernel(const float4* __restrict__ src,
                           __half* __restrict__ dst, int n4)
{
    int i = blockIdx.x * blockDim.x + threadIdx.x;
    if (i < n4) {
        float4 v = src[i];
        __half2* d = (__half2*)(dst + 4 * (size_t)i);
        d[0] = __floats2half2_rn(v.x, v.y);
        d[1] = __floats2half2_rn(v.z, v.w);
    }
}

// ---------------------------------------------------------------------------
// fp16 GEMM (unchanged): 128x256x32, cp.async double-buffer
// ---------------------------------------------------------------------------
__device__ __forceinline__ void cp_async16(void* smem, const void* gmem)
{
    uint32_t s = (uint32_t)__cvta_generic_to_shared(smem);
    asm volatile("cp.async.cg.shared.global [%0], [%1], 16;\n" :: "r"(s), "l"(gmem));
}

__device__ __forceinline__ void ldsm_x4(uint32_t* r, const void* p)
{
    uint32_t s = (uint32_t)__cvta_generic_to_shared(p);
    asm volatile("ldmatrix.sync.aligned.m8n8.x4.shared.b16 {%0,%1,%2,%3}, [%4];\n"
                 : "=r"(r[0]), "=r"(r[1]), "=r"(r[2]), "=r"(r[3]) : "r"(s));
}

__device__ __forceinline__ void mma16816(float* c, const uint32_t* a, const uint32_t* b)
{
    asm volatile(
        "mma.sync.aligned.m16n8k16.row.col.f32.f16.f16.f32 "
        "{%0,%1,%2,%3}, {%4,%5,%6,%7}, {%8,%9}, {%0,%1,%2,%3};\n"
        : "+f"(c[0]), "+f"(c[1]), "+f"(c[2]), "+f"(c[3])
        : "r"(a[0]), "r"(a[1]), "r"(a[2]), "r"(a[3]), "r"(b[0]), "r"(b[1]));
}

#define SROW 40
#define GA_H (128 * SROW)
#define GB_H (256 * SROW)
#define GEMM_SMEM ((2 * GA_H + 2 * GB_H) * 2)

extern __shared__ char dynsm[];

__global__ __launch_bounds__(256, 1) void gemm_fp16(
    const __half* __restrict__ Af, const __half* __restrict__ Bf,
    float* __restrict__ C)
{
    __half* As = (__half*)dynsm;
    __half* Bs = (__half*)dynsm + 2 * GA_H;

    const int tid  = threadIdx.x;
    const int wid  = tid >> 5, lane = tid & 31;
    const int wm   = wid >> 2, wn = wid & 3;
    const int bm   = blockIdx.y * 128, bn = blockIdx.x * 256;

    const int NIT = GK / 32;

    float acc[4][8][4];
    #pragma unroll
    for (int mi = 0; mi < 4; ++mi)
        #pragma unroll
        for (int ni = 0; ni < 8; ++ni)
            #pragma unroll
            for (int j = 0; j < 4; ++j) acc[mi][ni][j] = 0.0f;

    auto load_tiles = [&](int st, int it) {
        int kk = it * 32;
        #pragma unroll
        for (int j = 0; j < 2; ++j) {
            int c   = tid + j * 256;
            int row = c >> 2;
            int off = (c & 3) * 8;
            cp_async16(&As[st * GA_H + row * SROW + off],
                       Af + (size_t)(bm + row) * GK + kk + off);
        }
        #pragma unroll
        for (int j = 0; j < 4; ++j) {
            int c   = tid + j * 256;
            int row = c >> 2;
            int off = (c & 3) * 8;
            cp_async16(&Bs[st * GB_H + row * SROW + off],
                       Bf + (size_t)(bn + row) * GK + kk + off);
        }
        asm volatile("cp.async.commit_group;\n");
    };

    load_tiles(0, 0);

    for (int it = 0; it < NIT; ++it) {
        int st = it & 1;
        if (it + 1 < NIT) {
            load_tiles(st ^ 1, it + 1);
            asm volatile("cp.async.wait_group 1;\n");
        } else {
            asm volatile("cp.async.wait_group 0;\n");
        }
        __syncthreads();

        #pragma unroll
        for (int ks = 0; ks < 2; ++ks) {
            uint32_t a[4][4], b[8][2];
            int ra = wm * 64 + (lane & 7) + ((lane & 8) ? 8 : 0);
            int ca = ks * 16 + ((lane & 16) ? 8 : 0);
            #pragma unroll
            for (int mi = 0; mi < 4; ++mi)
                ldsm_x4(a[mi], &As[st * GA_H + (ra + mi * 16) * SROW + ca]);
            int rb = wn * 64 + (lane & 7) + ((lane & 16) ? 8 : 0);
            int cb = ks * 16 + ((lane & 8) ? 8 : 0);
            #pragma unroll
            for (int g = 0; g < 4; ++g) {
                uint32_t r[4];
                ldsm_x4(r, &Bs[st * GB_H + (rb + g * 16) * SROW + cb]);
                b[2 * g][0] = r[0]; b[2 * g][1] = r[1];
                b[2 * g + 1][0] = r[2]; b[2 * g + 1][1] = r[3];
            }
            #pragma unroll
            for (int mi = 0; mi < 4; ++mi)
                #pragma unroll
                for (int ni = 0; ni < 8; ++ni)
                    mma16816(acc[mi][ni], a[mi], b[ni]);
        }
        __syncthreads();
    }

    #pragma unroll
    for (int mi = 0; mi < 4; ++mi) {
        #pragma unroll
        for (int ni = 0; ni < 8; ++ni) {
            int row = bm + wm * 64 + mi * 16 + (lane >> 2);
            int col = bn + wn * 64 + ni * 8 + (lane & 3) * 2;
            float2* p0 = (float2*)(C + (size_t)row * GN + col);
            float2* p1 = (float2*)(C + (size_t)(row + 8) * GN + col);
            *p0 = make_float2(acc[mi][ni][0], acc[mi][ni][1]);
            *p1 = make_float2(acc[mi][ni][2], acc[mi][ni][3]);
        }
    }
}

// ---------------------------------------------------------------------------
// complex helpers
// ---------------------------------------------------------------------------
__device__ __forceinline__ float2 cadd(float2 a, float2 b)
{ return make_float2(a.x + b.x, a.y + b.y); }
__device__ __forceinline__ float2 csub(float2 a, float2 b)
{ return make_float2(a.x - b.x, a.y - b.y); }
__device__ __forceinline__ float2 cmul(float2 a, float2 b)
{ return make_float2(a.x * b.x - a.y * b.y, a.x * b.y + a.y * b.x); }
__device__ __forceinline__ float2 cmulc(float2 a, float2 b)   // a * conj(b)
{ return make_float2(a.x * b.x + a.y * b.y, a.y * b.x - a.x * b.y); }

// twiddle fetch with sign fold: table holds tw[k]=exp(-2pi i k/2048), k<1024
__device__ __forceinline__ float2 twget(const float2* tw, int e)
{
    float2 w = tw[e & 1023];
    if (e & 1024) { w.x = -w.x; w.y = -w.y; }
    return w;
}

// ---------------------------------------------------------------------------
// DFT-8 in registers (even/odd DFT-4 + W8 combine). INV = conjugated.
// ---------------------------------------------------------------------------
template<bool INV>
__device__ __forceinline__ void dft8(float2* a)
{
    const float C = 0.70710678118654752f;
    float2 t0 = cadd(a[0], a[4]), t1 = csub(a[0], a[4]);
    float2 t2 = cadd(a[2], a[6]), t3 = csub(a[2], a[6]);
    float2 u0 = cadd(a[1], a[5]), u1 = csub(a[1], a[5]);
    float2 u2 = cadd(a[3], a[7]), u3 = csub(a[3], a[7]);
    float2 E0 = cadd(t0, t2), E2 = csub(t0, t2);
    float2 O0 = cadd(u0, u2), O2 = csub(u0, u2);
    float2 E1, E3, O1, O3, w1o, w2o, w3o;
    if (!INV) {
        E1 = make_float2(t1.x + t3.y, t1.y - t3.x);   // t1 - i t3
        E3 = make_float2(t1.x - t3.y, t1.y + t3.x);
        O1 = make_float2(u1.x + u3.y, u1.y - u3.x);
        O3 = make_float2(u1.x - u3.y, u1.y + u3.x);
        w1o = make_float2(C * (O1.x + O1.y), C * (O1.y - O1.x));   // c(1-i)
        w2o = make_float2(O2.y, -O2.x);                            // -i
        w3o = make_float2(C * (O3.y - O3.x), -C * (O3.x + O3.y));  // -c(1+i)
    } else {
        E1 = make_float2(t1.x - t3.y, t1.y + t3.x);   // t1 + i t3
        E3 = make_float2(t1.x + t3.y, t1.y - t3.x);
        O1 = make_float2(u1.x - u3.y, u1.y + u3.x);
        O3 = make_float2(u1.x + u3.y, u1.y - u3.x);
        w1o = make_float2(C * (O1.x - O1.y), C * (O1.y + O1.x));   // c(1+i)
        w2o = make_float2(-O2.y, O2.x);                            // i
        w3o = make_float2(-C * (O3.x + O3.y), C * (O3.x - O3.y));  // -c(1-i)
    }
    a[0] = cadd(E0, O0); a[4] = csub(E0, O0);
    a[1] = cadd(E1, w1o); a[5] = csub(E1, w1o);
    a[2] = cadd(E2, w2o); a[6] = csub(E2, w2o);
    a[3] = cadd(E3, w3o); a[7] = csub(E3, w3o);
}

// One radix-8 Stockham stage (smem -> smem), m in {8, 64}
template<bool INV>
__device__ __forceinline__ void r8_stage(const float2* x, float2* y,
                                         const float2* tw, int tid, int m)
{
    int t = tid;
    int pm = t & ~(m - 1);
    float2 a[8];
    #pragma unroll
    for (int q = 0; q < 8; ++q) a[q] = x[SW(t + (q << 8))];
    dft8<INV>(a);
    int base = t + 7 * pm;
    y[SW(base)] = a[0];
    #pragma unroll
    for (int q = 1; q < 8; ++q) {
        float2 w = twget(tw, q * pm);
        y[SW(base + q * m)] = INV ? cmulc(a[q], w) : cmul(w, a[q]);
    }
}

// ---------------------------------------------------------------------------
// Block reduction of (sr, si, sq) -> f = 2/sq * (sr, si)   (8 warps)
// ---------------------------------------------------------------------------
__device__ __forceinline__ float2 block_reduce_f(
    float sr, float si, float sq, float (*red)[8], int tid)
{
    #pragma unroll
    for (int o = 16; o; o >>= 1) {
        sr += __shfl_xor_sync(0xffffffffu, sr, o);
        si += __shfl_xor_sync(0xffffffffu, si, o);
        sq += __shfl_xor_sync(0xffffffffu, sq, o);
    }
    int w = tid >> 5;
    if ((tid & 31) == 0) { red[0][w] = sr; red[1][w] = si; red[2][w] = sq; }
    __syncthreads();
    sr = si = sq = 0.f;
    #pragma unroll
    for (int i = 0; i < 8; ++i) { sr += red[0][i]; si += red[1][i]; sq += red[2][i]; }
    __syncthreads();
    float f = 2.0f / sq;
    return make_float2(f * sr, f * si);
}

// ---------------------------------------------------------------------------
// Fused URNN pipeline. 1 CTA = 1 row. Radix-8 Stockham (8,8,8,4).
// ---------------------------------------------------------------------------
__global__ __launch_bounds__(FT, 5) void urnn_fused_kernel(
    const float* __restrict__ state, const float* __restrict__ gin,
    const float* __restrict__ b_h,
    const float* __restrict__ d1w, const float* __restrict__ r1re, const float* __restrict__ r1im,
    const float* __restrict__ d2w, const float* __restrict__ r2re, const float* __restrict__ r2im,
    const float* __restrict__ d3w, const int* __restrict__ perm,
    float* __restrict__ out)
{
    __shared__ float2 bA[FN];
    __shared__ float2 bB[FN];
    __shared__ float2 tws[1024];
    __shared__ float  red[3][8];

    const int tid = threadIdx.x;
    const size_t b = blockIdx.x;
    const float* srow = state + b * (2 * FN);
    const float* grow = gin   + b * (2 * FN);
    float*       orow = out   + b * (2 * FN);

    for (int i = tid; i < 1024; i += FT) {
        float s, c;
        __sincosf(-6.283185307179586f * (float)i / (float)FN, &s, &c);
        tws[i] = make_float2(c, s);
    }
    __syncthreads();

    float2 *x = bA, *y = bB;

    // ---- FWD stage 0 (m=1, radix-8) fused with global load + diag1 ----
    {
        int t = tid;
        float2 a[8];
        #pragma unroll
        for (int q = 0; q < 8; ++q) {
            int i = t + (q << 8);
            float re = srow[i], im = srow[FN + i];
            float s, c; __sincosf(d1w[i], &s, &c);
            a[q] = make_float2(c * re - s * im, s * re + c * im);
        }
        dft8<false>(a);
        int base = 8 * t;
        y[SW(base)] = a[0];
        #pragma unroll
        for (int q = 1; q < 8; ++q)
            y[SW(base + q)] = cmul(twget(tws, q * t), a[q]);
    }
    __syncthreads();
    { float2* tmp = x; x = y; y = tmp; }

    // ---- FWD stages m=8, m=64 ----
    r8_stage<false>(x, y, tws, tid, 8);
    __syncthreads();
    { float2* tmp = x; x = y; y = tmp; }
    r8_stage<false>(x, y, tws, tid, 64);
    __syncthreads();
    { float2* tmp = x; x = y; y = tmp; }

    // ---- FWD radix-4 tail (m=512, no twiddles) fused with reflect-1 dots ----
    float sr1 = 0.f, si1 = 0.f, sq1 = 0.f;
    #pragma unroll
    for (int k = 0; k < 2; ++k) {
        int t = tid + k * 256;
        float2 a0 = x[SW(t)], a1 = x[SW(t + 512)],
               a2 = x[SW(t + 1024)], a3 = x[SW(t + 1536)];
        float2 t0 = cadd(a0, a2), t1 = csub(a0, a2);
        float2 t2 = cadd(a1, a3), t3 = csub(a1, a3);
        float2 b0 = cadd(t0, t2);
        float2 b2 = csub(t0, t2);
        float2 b1 = make_float2(t1.x + t3.y, t1.y - t3.x);
        float2 b3 = make_float2(t1.x - t3.y, t1.y + t3.x);
        y[SW(t)]        = b0;
        y[SW(t + 512)]  = b1;
        y[SW(t + 1024)] = b2;
        y[SW(t + 1536)] = b3;
        float2 bb[4] = {b0, b1, b2, b3};
        #pragma unroll
        for (int q = 0; q < 4; ++q) {
            int i = t + q * 512;
            float vr = r1re[i], vi = r1im[i];
            sr1 += bb[q].x * vr + bb[q].y * vi;
            si1 += bb[q].y * vr - bb[q].x * vi;
            sq1 += vr * vr + vi * vi;
        }
    }
    __syncthreads();
    { float2* tmp = x; x = y; y = tmp; }

    float2 f1 = block_reduce_f(sr1, si1, sq1, red, tid);

    // ---- IFFT stage 0 (m=1) fused with reflect1-update + perm + diag2 ----
    {
        int t = tid;
        float2 a[8];
        #pragma unroll
        for (int q = 0; q < 8; ++q) {
            int i = t + (q << 8);
            int p = perm[i];
            float2 zp = x[SW(p)];
            float vr = r1re[p], vi = r1im[p];
            zp.x -= f1.x * vr - f1.y * vi;
            zp.y -= f1.x * vi + f1.y * vr;
            float s, c; __sincosf(d2w[i], &s, &c);
            a[q] = make_float2(c * zp.x - s * zp.y, s * zp.x + c * zp.y);
        }
        dft8<true>(a);
        int base = 8 * t;
        y[SW(base)] = a[0];
        #pragma unroll
        for (int q = 1; q < 8; ++q)
            y[SW(base + q)] = cmulc(a[q], twget(tws, q * t));
    }
    __syncthreads();
    { float2* tmp = x; x = y; y = tmp; }

    // ---- IFFT stages m=8, m=64 ----
    r8_stage<true>(x, y, tws, tid, 8);
    __syncthreads();
    { float2* tmp = x; x = y; y = tmp; }
    r8_stage<true>(x, y, tws, tid, 64);
    __syncthreads();
    { float2* tmp = x; x = y; y = tmp; }

    // ---- IFFT radix-4 tail fused with reflect-2 dots ----
    float sr2 = 0.f, si2 = 0.f, sq2 = 0.f;
    #pragma unroll
    for (int k = 0; k < 2; ++k) {
        int t = tid + k * 256;
        float2 a0 = x[SW(t)], a1 = x[SW(t + 512)],
               a2 = x[SW(t + 1024)], a3 = x[SW(t + 1536)];
        float2 t0 = cadd(a0, a2), t1 = csub(a0, a2);
        float2 t2 = cadd(a1, a3), t3 = csub(a1, a3);
        float2 b0 = cadd(t0, t2);
        float2 b2 = csub(t0, t2);
        float2 b1 = make_float2(t1.x - t3.y, t1.y + t3.x);   // inverse: t1 + i t3
        float2 b3 = make_float2(t1.x + t3.y, t1.y - t3.x);
        y[SW(t)]        = b0;
        y[SW(t + 512)]  = b1;
        y[SW(t + 1024)] = b2;
        y[SW(t + 1536)] = b3;
        float2 bb[4] = {b0, b1, b2, b3};
        #pragma unroll
        for (int q = 0; q < 4; ++q) {
            int i = t + q * 512;
            float vr = r2re[i], vi = r2im[i];
            sr2 += bb[q].x * vr + bb[q].y * vi;
            si2 += bb[q].y * vr - bb[q].x * vi;
            sq2 += vr * vr + vi * vi;
        }
    }
    __syncthreads();
    { float2* tmp = x; x = y; y = tmp; }

    float2 f2 = block_reduce_f(sr2, si2, sq2, red, tid);

    // ---- final: reflect2-update + diag3*(1/N) + add inputs + modReLU ----
    const float invN = 1.0f / (float)FN;
    for (int i = tid; i < FN; i += FT) {
        float2 zc = x[SW(i)];
        float vr = r2re[i], vi = r2im[i];
        zc.x -= f2.x * vr - f2.y * vi;
        zc.y -= f2.x * vi + f2.y * vr;
        float s, c; __sincosf(d3w[i], &s, &c);
        float zr = (c * zc.x - s * zc.y) * invN;
        float zi = (s * zc.x + c * zc.y) * invN;
        float pr = grow[i]      + zr;
        float pi = grow[FN + i] + zi;
        float norm = sqrtf(pr * pr + pi * pi);
        float sc = fmaxf(norm + b_h[i], 0.0f) / (norm + 1e-6f);
        orow[i]      = pr * sc;
        orow[FN + i] = pi * sc;
    }
}

// ---------------------------------------------------------------------------
// Launch
// ---------------------------------------------------------------------------
extern "C" void kernel_launch(void* const* d_in, const int* in_sizes, int n_in,
                              void* d_out, int out_size)
{
    const float* inputs = (const float*)d_in[0];
    const float* state  = (const float*)d_in[1];
    const float* w_ih   = (const float*)d_in[2];
    const float* b_h    = (const float*)d_in[3];
    const float* d1w    = (const float*)d_in[4];
    const float* r1re   = (const float*)d_in[5];
    const float* r1im   = (const float*)d_in[6];
    const float* d2w    = (const float*)d_in[7];
    const float* r2re   = (const float*)d_in[8];
    const float* r2im   = (const float*)d_in[9];
    const float* d3w    = (const float*)d_in[10];
    const int*   perm   = (const int*)d_in[11];
    float* out = (float*)d_out;

    float *gmul; __half *Af, *Bf;
    cudaGetSymbolAddress((void**)&gmul, g_mul);
    cudaGetSymbolAddress((void**)&Af, g_Af);
    cudaGetSymbolAddress((void**)&Bf, g_Bf);

    cvt_kernel<<<(GM * GK / 4) / 256, 256>>>((const float4*)inputs, Af, GM * GK / 4);
    cvt_kernel<<<(GN * GK / 4) / 256, 256>>>((const float4*)w_ih,   Bf, GN * GK / 4);

    static bool attr_set = false;
    if (!attr_set) {
        cudaFuncSetAttribute(gemm_fp16, cudaFuncAttributeMaxDynamicSharedMemorySize,
                             GEMM_SMEM);
        attr_set = true;
    }
    dim3 ggrid(GN / 256, GM / 128);
    gemm_fp16<<<ggrid, 256, GEMM_SMEM>>>(Af, Bf, gmul);

    urnn_fused_kernel<<<GM, FT>>>(state, gmul, b_h,
                                  d1w, r1re, r1im,
                                  d2w, r2re, r2im,
                                  d3w, perm, out);
}